// round 16
// baseline (speedup 1.0000x reference)
#include <cuda_runtime.h>
#include <math.h>

#define NB 30
#define NODES 135
#define NROWS (NB*NODES)     // 4050
#define NPAIRS 9045
#define TOTPAIR (NB*NPAIRS)  // 271350

#define BN_S 0.9999950001f   // 1/sqrt(1+1e-5)
#define RRELU_S 0.2291666667f

#define K4_SPLIT 9
#define K6_SPLIT 16

typedef unsigned long long u64;

// ---- packed fp32x2 helpers (Blackwell FFMA2 path) ----
__device__ __forceinline__ u64 pk(float lo, float hi){
    u64 r; asm("mov.b64 %0, {%1,%2};" : "=l"(r) : "f"(lo), "f"(hi)); return r;
}
__device__ __forceinline__ void upk(u64 v, float& lo, float& hi){
    asm("mov.b64 {%0,%1}, %2;" : "=f"(lo), "=f"(hi) : "l"(v));
}
__device__ __forceinline__ u64 fma2(u64 a, u64 b, u64 c){
    u64 d; asm("fma.rn.f32x2 %0, %1, %2, %3;" : "=l"(d) : "l"(a), "l"(b), "l"(c)); return d;
}
__device__ __forceinline__ u64 add2(u64 a, u64 b){
    u64 d; asm("add.rn.f32x2 %0, %1, %2;" : "=l"(d) : "l"(a), "l"(b)); return d;
}

// ---- scratch ----
__device__ float g_s3[NROWS*48*45];          // [n][c*45+l]
__device__ float g_feats[NROWS*32];
__device__ float g_subj[NB*NPAIRS];
__device__ float g_p4[K4_SPLIT*NROWS*32];
__device__ float g_part[K6_SPLIT*NB*1024];
__device__ float g_c1[NB*1024];
__device__ float g_c2[NB*256];
__device__ float g_c3[NB*64];

__device__ __forceinline__ float leaky(float v){ return v > 0.f ? v : 0.01f*v; }

// ============================================================
// KCONV: fused conv1+conv2+conv3 per row. 384 threads (R10/R15 winner).
// Dynamic smem 49024 B, phase-aliased. FROZEN.
// ============================================================
__global__ void kconv(const float* __restrict__ x,
      const float* __restrict__ w1, const float* __restrict__ cb1,
      const float* __restrict__ g1, const float* __restrict__ bb1,
      const float* __restrict__ w2, const float* __restrict__ cb2,
      const float* __restrict__ g2, const float* __restrict__ bb2,
      const float* __restrict__ w3, const float* __restrict__ cb3,
      const float* __restrict__ g3, const float* __restrict__ bb3){
    extern __shared__ float dsm[];
    float* s2s = dsm;                           // [0, 2944)
    float* s1s = dsm + 2944;                    // [2944, 5920) (phase A)
    u64*   wp2 = (u64*)(dsm + 2944 + 2976);     // 1568 u64 (phase A)
    u64*   wp3 = (u64*)(dsm + 2944);            // 4656 u64 (phase B)

    __shared__ float xr[376];
    __shared__ float ws1[96], A1[32], B1[32], A2[64], B2[64];

    int n = blockIdx.x, tid = threadIdx.x;
    const int NT = 384;

    for (int i=tid;i<375;i+=NT) xr[i] = x[n*375+i];
    if (tid < 96) ws1[tid] = w1[tid];
    if (tid < 32){ float a = g1[tid]*BN_S; A1[tid]=a; B1[tid]=fmaf(cb1[tid],a,bb1[tid]); }
    if (tid < 64){ float a = g2[tid]*BN_S; A2[tid]=a; B2[tid]=fmaf(cb2[tid],a,bb2[tid]); }
    for (int i=tid;i<1536;i+=NT){
        int c = i/48, r = i%48;
        wp2[c*49+r] = pk(w2[(2*c)*48 + r], w2[(2*c+1)*48 + r]);
    }
    __syncthreads();

    // ---- stage 1: x(375) -> s1s(16,186) ----
    for (int t=tid;t<2976;t+=NT){
        int c = t/186, l = t%186;
        float x0=xr[2*l], x1=xr[2*l+1], x2=xr[2*l+2], x3=xr[2*l+3];
        int c0=2*c, c1=2*c+1;
        float wa0=ws1[c0*3],wa1=ws1[c0*3+1],wa2=ws1[c0*3+2];
        float wb0=ws1[c1*3],wb1=ws1[c1*3+1],wb2=ws1[c1*3+2];
        float p00 = x0*wa0 + x1*wa1 + x2*wa2;
        float p01 = x1*wa0 + x2*wa1 + x3*wa2;
        float p10 = x0*wb0 + x1*wb1 + x2*wb2;
        float p11 = x1*wb0 + x2*wb1 + x3*wb2;
        float a0=A1[c0],b0=B1[c0],a1=A1[c1],b1=B1[c1];
        float v = fmaxf(fmaxf(leaky(fmaf(p00,a0,b0)), leaky(fmaf(p01,a0,b0))),
                        fmaxf(leaky(fmaf(p10,a1,b1)), leaky(fmaf(p11,a1,b1))));
        s1s[c*186+l] = v;
    }
    __syncthreads();

    // ---- stage 2: s1s(16,186) -> s2s(32,92). 368 tasks, 1 pass ----
    if (tid < 368){
        int c2 = tid & 15, lt = tid >> 4;
        int l0 = lt*4, px = 2*l0;
        u64 acA[8], acB[8];
        #pragma unroll
        for (int p=0;p<8;p++){ acA[p]=0ULL; acB[p]=0ULL; }
        const u64* wA = wp2 + c2*49;
        const u64* wB = wp2 + (c2+16)*49;
        for (int ci=0; ci<16; ci++){
            const float2* xp = (const float2*)(s1s + ci*186 + px);
            float xv[10];
            #pragma unroll
            for (int q=0;q<5;q++){ float2 v2 = xp[q]; xv[2*q]=v2.x; xv[2*q+1]=v2.y; }
            u64 xd[10];
            #pragma unroll
            for (int q=0;q<10;q++) xd[q] = pk(xv[q],xv[q]);
            u64 a0 = wA[ci*3], a1 = wA[ci*3+1], a2 = wA[ci*3+2];
            u64 b0 = wB[ci*3], b1 = wB[ci*3+1], b2 = wB[ci*3+2];
            #pragma unroll
            for (int p=0;p<8;p++){
                acA[p] = fma2(xd[p],a0, fma2(xd[p+1],a1, fma2(xd[p+2],a2, acA[p])));
                acB[p] = fma2(xd[p],b0, fma2(xd[p+1],b1, fma2(xd[p+2],b2, acB[p])));
            }
        }
        #pragma unroll
        for (int h=0;h<2;h++){
            int cp = c2 + 16*h;
            u64* ac = h ? acB : acA;
            float a0=A2[2*cp],b0=B2[2*cp],a1=A2[2*cp+1],b1=B2[2*cp+1];
            #pragma unroll
            for (int q=0;q<4;q++){
                float e0,o0,e1,o1;
                upk(ac[2*q], e0, o0);
                upk(ac[2*q+1], e1, o1);
                float v = fmaxf(fmaxf(leaky(fmaf(e0,a0,b0)), leaky(fmaf(e1,a0,b0))),
                                fmaxf(leaky(fmaf(o0,a1,b1)), leaky(fmaf(o1,a1,b1))));
                s2s[cp*92 + l0+q] = v;
            }
        }
    }
    __syncthreads();

    // ---- phase B weights ----
    for (int i=tid;i<4608;i+=NT){
        int c = i/96, r = i%96;
        wp3[c*97+r] = pk(w3[(2*c)*96 + r], w3[(2*c+1)*96 + r]);
    }
    __syncthreads();

    // ---- stage 3: s2s(32,92) -> g_s3. 24 grp(2 pairs) x 15 lt = 360 ----
    if (tid < 360){
        int g = tid % 24, lt = tid / 24;
        int l0 = lt*3, px = 2*l0;
        u64 ac[2][6];
        #pragma unroll
        for (int h=0;h<2;h++)
            #pragma unroll
            for (int p=0;p<6;p++) ac[h][p]=0ULL;
        const u64* wA = wp3 + (2*g)*97;
        const u64* wB = wp3 + (2*g+1)*97;
        for (int ci=0; ci<32; ci++){
            const float2* xp = (const float2*)(s2s + ci*92 + px);
            float xv[8];
            #pragma unroll
            for (int q=0;q<4;q++){ float2 v2 = xp[q]; xv[2*q]=v2.x; xv[2*q+1]=v2.y; }
            u64 xd[8];
            #pragma unroll
            for (int q=0;q<8;q++) xd[q] = pk(xv[q],xv[q]);
            u64 a0 = wA[ci*3], a1 = wA[ci*3+1], a2 = wA[ci*3+2];
            u64 b0 = wB[ci*3], b1 = wB[ci*3+1], b2 = wB[ci*3+2];
            #pragma unroll
            for (int p=0;p<6;p++){
                ac[0][p] = fma2(xd[p],a0, fma2(xd[p+1],a1, fma2(xd[p+2],a2, ac[0][p])));
                ac[1][p] = fma2(xd[p],b0, fma2(xd[p+1],b1, fma2(xd[p+2],b2, ac[1][p])));
            }
        }
        #pragma unroll
        for (int h=0;h<2;h++){
            int cp = 2*g + h;
            int c0=2*cp, c1=2*cp+1;
            float a0=__ldg(g3+c0)*BN_S, a1=__ldg(g3+c1)*BN_S;
            float b0=fmaf(__ldg(cb3+c0),a0,__ldg(bb3+c0));
            float b1=fmaf(__ldg(cb3+c1),a1,__ldg(bb3+c1));
            #pragma unroll
            for (int q=0;q<3;q++){
                float e0,o0,e1,o1;
                upk(ac[h][2*q], e0, o0);
                upk(ac[h][2*q+1], e1, o1);
                float v = fmaxf(fmaxf(leaky(fmaf(e0,a0,b0)), leaky(fmaf(e1,a0,b0))),
                                fmaxf(leaky(fmaf(o0,a1,b1)), leaky(fmaf(o1,a1,b1))));
                g_s3[(n*48+cp)*45 + l0+q] = v;
            }
        }
    }
}

// ============================================================
// K4a: split-K GEMM: s3(4050,2160) @ W(2160,32), smem h-tile,
// register double-buffered h prefetch (3 float4/thread).
// ============================================================
__global__ void k4a(const float* __restrict__ w){
    __shared__ float h_s[64*52];        // 13312 B
    __shared__ u64   ws2[48*16];        // 6144 B
    int tid = threadIdx.x;
    int o4 = tid & 7, rg = tid >> 3;
    int n0 = blockIdx.x * 64;
    int r0 = 2*rg, r1 = 2*rg+1;
    int ks = blockIdx.y * 240;

    // fixed h-load slots: items tid, tid+256, tid+512 (768 = 64 rows x 12 f4)
    int hrow[3], hcol[3];
    const float* hbase[3];
    #pragma unroll
    for (int q=0;q<3;q++){
        int i = tid + q*256;
        hrow[q] = i / 12; hcol[q] = i % 12;
        int nn = n0 + hrow[q]; if (nn >= NROWS) nn = NROWS-1;
        hbase[q] = g_s3 + (size_t)nn*2160 + ks + 4*hcol[q];
    }
    float4 hreg[3];
    #pragma unroll
    for (int q=0;q<3;q++) hreg[q] = *(const float4*)(hbase[q]);

    u64 a00=0ULL, a01=0ULL, a10=0ULL, a11=0ULL;
    for (int c0 = 0; c0 < 240; c0 += 48){
        __syncthreads();
        // stage weights (L2-hot)
        for (int i = tid; i < 384; i += 256){
            int kk = i >> 3, j = i & 7;
            float4 f = ((const float4*)(w + (ks + c0 + kk)*32))[j];
            ws2[kk*16 + 2*j]   = pk(f.x, f.y);
            ws2[kk*16 + 2*j+1] = pk(f.z, f.w);
        }
        // store prefetched h tile
        #pragma unroll
        for (int q=0;q<3;q++)
            *(float4*)(h_s + hrow[q]*52 + 4*hcol[q]) = hreg[q];
        // prefetch next chunk
        if (c0 + 48 < 240){
            #pragma unroll
            for (int q=0;q<3;q++) hreg[q] = *(const float4*)(hbase[q] + c0 + 48);
        }
        __syncthreads();
        #pragma unroll
        for (int kk = 0; kk < 48; kk++){
            ulonglong2 wv = *(const ulonglong2*)&ws2[kk*16 + 2*o4];
            float ha = h_s[r0*52 + kk];
            float hb = h_s[r1*52 + kk];
            u64 had = pk(ha, ha), hbd = pk(hb, hb);
            a00 = fma2(had, wv.x, a00);
            a01 = fma2(had, wv.y, a01);
            a10 = fma2(hbd, wv.x, a10);
            a11 = fma2(hbd, wv.y, a11);
        }
    }
    float e0,o0,e1,o1;
    int n = n0 + r0;
    if (n < NROWS){
        upk(a00, e0, o0); upk(a01, e1, o1);
        *(float4*)(g_p4 + ((size_t)blockIdx.y*NROWS + n)*32 + 4*o4) = make_float4(e0,o0,e1,o1);
    }
    n = n0 + r1;
    if (n < NROWS){
        upk(a10, e0, o0); upk(a11, e1, o1);
        *(float4*)(g_p4 + ((size_t)blockIdx.y*NROWS + n)*32 + 4*o4) = make_float4(e0,o0,e1,o1);
    }
}

__global__ void k4b(const float* __restrict__ b){
    int idx = blockIdx.x*blockDim.x + threadIdx.x;
    if (idx >= NROWS*32) return;
    int o = idx & 31;
    float s = b[o];
    #pragma unroll
    for (int q=0;q<K4_SPLIT;q++) s += g_p4[(size_t)q*NROWS*32 + idx];
    g_feats[idx] = s;
}

// ============================================================
// K5: sim MLP, 2 pairs per thread (R10/R15 winner). FROZEN.
// ============================================================
__device__ __forceinline__ void decode_pair(int pp, int& b, int& i, int& j){
    b = pp / NPAIRS;
    int p = pp - b*NPAIRS;
    int ii = (int)((269.0f - sqrtf(72361.0f - 8.0f*(float)p)) * 0.5f);
    if (ii < 0) ii = 0; if (ii > 133) ii = 133;
    while (ii > 0   && (ii*(269-ii))/2 > p) ii--;
    while (ii < 133 && ((ii+1)*(268-ii))/2 <= p) ii++;
    i = ii;
    j = ii + 1 + (p - (ii*(269-ii))/2);
}

__global__ void k5(const float* __restrict__ w1, const float* __restrict__ b1,
                   const float* __restrict__ w2, const float* __restrict__ b2,
                   const float* __restrict__ w3, const float* __restrict__ b3,
                   const float* __restrict__ w4, const float* __restrict__ b4){
    __shared__ u64 w1u[1024], w2u[256], w3u[64];
    __shared__ float w4s[8], b1s[32], b2s[16], b3s[8];
    __shared__ float b4s;
    int tid = threadIdx.x;
    for (int i=tid;i<1024;i+=256){ float2 v = *(const float2*)(w1+2*i); w1u[i]=pk(v.x,v.y); }
    if (tid<256){ float2 v = *(const float2*)(w2+2*tid); w2u[tid]=pk(v.x,v.y); }
    if (tid<64) { float2 v = *(const float2*)(w3+2*tid); w3u[tid]=pk(v.x,v.y); }
    if (tid<32)  b1s[tid]=b1[tid];
    if (tid<16)  b2s[tid]=b2[tid];
    if (tid<8)   { w4s[tid]=w4[tid]; b3s[tid]=b3[tid]; }
    if (tid==0)  b4s=b4[0];
    __syncthreads();
    int gid = blockIdx.x*blockDim.x + tid;
    int p0 = gid*2;
    if (p0 >= TOTPAIR) return;
    int p1 = p0 + 1;
    bool has1 = p1 < TOTPAIR;
    int pb1 = has1 ? p1 : p0;
    int b0i,i0,j0, b1i,i1,j1;
    decode_pair(p0, b0i, i0, j0);
    decode_pair(pb1, b1i, i1, j1);
    const float4* fi0 = (const float4*)(g_feats + (b0i*135+i0)*32);
    const float4* fj0 = (const float4*)(g_feats + (b0i*135+j0)*32);
    const float4* fi1 = (const float4*)(g_feats + (b1i*135+i1)*32);
    const float4* fj1 = (const float4*)(g_feats + (b1i*135+j1)*32);

    u64 A0[16], A1[16];
    #pragma unroll
    for (int o=0;o<16;o++){ u64 bb = pk(b1s[2*o], b1s[2*o+1]); A0[o]=bb; A1[o]=bb; }
    #pragma unroll
    for (int q=0;q<8;q++){
        float4 f0 = fi0[q], f1 = fi1[q];
        float fv0[4] = {f0.x,f0.y,f0.z,f0.w};
        float fv1[4] = {f1.x,f1.y,f1.z,f1.w};
        #pragma unroll
        for (int s=0;s<4;s++){
            u64 v0 = pk(fv0[s], fv0[s]);
            u64 v1 = pk(fv1[s], fv1[s]);
            int t = 4*q+s;
            #pragma unroll
            for (int o=0;o<16;o++){
                u64 ww = w1u[t*16+o];
                A0[o] = fma2(v0, ww, A0[o]);
                A1[o] = fma2(v1, ww, A1[o]);
            }
        }
    }
    #pragma unroll
    for (int q=0;q<8;q++){
        float4 f0 = fj0[q], f1 = fj1[q];
        float fv0[4] = {f0.x,f0.y,f0.z,f0.w};
        float fv1[4] = {f1.x,f1.y,f1.z,f1.w};
        #pragma unroll
        for (int s=0;s<4;s++){
            u64 v0 = pk(fv0[s], fv0[s]);
            u64 v1 = pk(fv1[s], fv1[s]);
            int t = 32 + 4*q+s;
            #pragma unroll
            for (int o=0;o<16;o++){
                u64 ww = w1u[t*16+o];
                A0[o] = fma2(v0, ww, A0[o]);
                A1[o] = fma2(v1, ww, A1[o]);
            }
        }
    }
    float h10[32], h11[32];
    #pragma unroll
    for (int o=0;o<16;o++){
        float e,od;
        upk(A0[o],e,od); h10[2*o]=fmaxf(e,0.f); h10[2*o+1]=fmaxf(od,0.f);
        upk(A1[o],e,od); h11[2*o]=fmaxf(e,0.f); h11[2*o+1]=fmaxf(od,0.f);
    }
    u64 B0[8], B1[8];
    #pragma unroll
    for (int o=0;o<8;o++){ u64 bb = pk(b2s[2*o], b2s[2*o+1]); B0[o]=bb; B1[o]=bb; }
    #pragma unroll
    for (int t=0;t<32;t++){
        u64 v0 = pk(h10[t], h10[t]);
        u64 v1 = pk(h11[t], h11[t]);
        #pragma unroll
        for (int o=0;o<8;o++){
            u64 ww = w2u[t*8+o];
            B0[o] = fma2(v0, ww, B0[o]);
            B1[o] = fma2(v1, ww, B1[o]);
        }
    }
    float h20[16], h21[16];
    #pragma unroll
    for (int o=0;o<8;o++){
        float e,od;
        upk(B0[o],e,od); h20[2*o]=fmaxf(e,0.f); h20[2*o+1]=fmaxf(od,0.f);
        upk(B1[o],e,od); h21[2*o]=fmaxf(e,0.f); h21[2*o+1]=fmaxf(od,0.f);
    }
    u64 C0[4], C1[4];
    #pragma unroll
    for (int o=0;o<4;o++){ u64 bb = pk(b3s[2*o], b3s[2*o+1]); C0[o]=bb; C1[o]=bb; }
    #pragma unroll
    for (int t=0;t<16;t++){
        u64 v0 = pk(h20[t], h20[t]);
        u64 v1 = pk(h21[t], h21[t]);
        #pragma unroll
        for (int o=0;o<4;o++){
            u64 ww = w3u[t*4+o];
            C0[o] = fma2(v0, ww, C0[o]);
            C1[o] = fma2(v1, ww, C1[o]);
        }
    }
    float o40 = b4s, o41 = b4s;
    #pragma unroll
    for (int o=0;o<4;o++){
        float e,od;
        upk(C0[o],e,od);
        o40 = fmaf(fmaxf(e,0.f),  w4s[2*o],   o40);
        o40 = fmaf(fmaxf(od,0.f), w4s[2*o+1], o40);
        upk(C1[o],e,od);
        o41 = fmaf(fmaxf(e,0.f),  w4s[2*o],   o41);
        o41 = fmaf(fmaxf(od,0.f), w4s[2*o+1], o41);
    }
    g_subj[p0] = tanhf(o40);
    if (has1) g_subj[p1] = tanhf(o41);
}

// ============================================================
// K6a: split-K GEMM partials: (30,9045)@(9045,1024).
// W tile register double-buffered (4 float4/thread prefetch).
// ============================================================
__global__ void k6a(const float* __restrict__ w){
    __shared__ __align__(16) char sbuf[33792];
    u64*   ssub2 = (u64*)sbuf;                 // 128*17 u64 = 17408 B
    float* wt    = (float*)(sbuf + 17408);     // 128*32 f   = 16384 B
    u64*   red   = (u64*)sbuf;                 // 256*15 u64 = 30720 B (post-loop)
    int tid = threadIdx.x;
    int lane = tid & 31, kg = tid >> 5;
    int nb = blockIdx.x*32;
    int kstart = blockIdx.y*566;
    int kend = min(9045, kstart+566);

    // fixed W-load slots: items tid + q*256 (1024 = 128 rows x 8 f4)
    int wkk[4], wj[4];
    #pragma unroll
    for (int q=0;q<4;q++){ int i = tid + q*256; wkk[q] = i>>3; wj[q] = i&7; }
    float4 wreg[4];
    {
        int clen0 = min(128, kend - kstart);
        #pragma unroll
        for (int q=0;q<4;q++){
            wreg[q] = make_float4(0.f,0.f,0.f,0.f);
            if (wkk[q] < clen0)
                wreg[q] = ((const float4*)(w + (size_t)(kstart + wkk[q])*1024 + nb))[wj[q]];
        }
    }

    u64 accp[15];
    #pragma unroll
    for (int m=0;m<15;m++) accp[m]=0ULL;
    for (int k0=kstart;k0<kend;k0+=128){
        int clen = min(128, kend-k0);
        __syncthreads();
        for (int i=tid;i<15*128;i+=256){
            int m = i>>7, kk = i&127;
            float v0=0.f, v1=0.f;
            if (kk<clen){
                v0 = g_subj[(2*m)*9045 + k0+kk];
                v1 = g_subj[(2*m+1)*9045 + k0+kk];
            }
            ssub2[kk*17+m] = pk(v0,v1);
        }
        // store prefetched W tile
        #pragma unroll
        for (int q=0;q<4;q++)
            ((float4*)(wt + wkk[q]*32))[wj[q]] = wreg[q];
        // prefetch next chunk's W
        int k1 = k0 + 128;
        if (k1 < kend){
            int clen1 = min(128, kend - k1);
            #pragma unroll
            for (int q=0;q<4;q++){
                wreg[q] = make_float4(0.f,0.f,0.f,0.f);
                if (wkk[q] < clen1)
                    wreg[q] = ((const float4*)(w + (size_t)(k1 + wkk[q])*1024 + nb))[wj[q]];
            }
        }
        __syncthreads();
        for (int kk=kg; kk<clen; kk+=8){
            float wv = wt[kk*32 + lane];
            u64 wv2 = pk(wv,wv);
            #pragma unroll
            for (int m=0;m<15;m++) accp[m] = fma2(ssub2[kk*17+m], wv2, accp[m]);
        }
    }
    __syncthreads();
    #pragma unroll
    for (int m=0;m<15;m++) red[tid*15+m] = accp[m];
    __syncthreads();
    for (int it=tid; it<32*15; it+=256){
        int l2 = it/15, mp = it%15;
        u64 s = red[l2*15+mp];
        #pragma unroll
        for (int q=1;q<8;q++) s = add2(s, red[(q*32+l2)*15+mp]);
        float e,o; upk(s,e,o);
        g_part[((size_t)blockIdx.y*30+2*mp)*1024   + nb + l2] = e;
        g_part[((size_t)blockIdx.y*30+2*mp+1)*1024 + nb + l2] = o;
    }
}

__global__ void k6b(const float* __restrict__ b){
    int idx = blockIdx.x*blockDim.x+threadIdx.x;
    if (idx >= 30*1024) return;
    int m = idx>>10, o = idx&1023;
    float s = b[o];
    #pragma unroll
    for (int q=0;q<K6_SPLIT;q++) s += g_part[((size_t)q*30+m)*1024+o];
    g_c1[idx] = (s >= 0.f) ? s : RRELU_S*s;
}

__global__ void k6c(const float* __restrict__ w, const float* __restrict__ b){
    __shared__ float red[256];
    int m = blockIdx.x, og = blockIdx.y;
    int tid = threadIdx.x;
    int ol = tid & 31, kg = tid >> 5;
    int o = og*32 + ol;
    const float* c1 = g_c1 + m*1024;
    float acc = 0.f;
    #pragma unroll 8
    for (int k = kg; k < 1024; k += 8)
        acc = fmaf(c1[k], w[k*256 + o], acc);
    red[tid] = acc;
    __syncthreads();
    if (tid < 32){
        float s = b[og*32 + tid];
        #pragma unroll
        for (int q=0;q<8;q++) s += red[q*32 + tid];
        g_c2[m*256 + og*32 + tid] = fmaxf(s, 0.f);
    }
}

__global__ void k6d(const float* __restrict__ w, const float* __restrict__ b){
    __shared__ float red[256];
    int m = blockIdx.x;
    int tid = threadIdx.x;
    int o = tid & 63, kg = tid >> 6;
    const float* c2 = g_c2 + m*256;
    float acc = 0.f;
    #pragma unroll 8
    for (int k = kg; k < 256; k += 4)
        acc = fmaf(c2[k], w[k*64 + o], acc);
    red[tid] = acc;
    __syncthreads();
    if (tid < 64){
        float s = b[tid] + red[tid] + red[64+tid] + red[128+tid] + red[192+tid];
        g_c3[m*64 + tid] = fmaxf(s, 0.f);
    }
}

__global__ void k6e(const float* __restrict__ w, const float* __restrict__ b,
                    float* __restrict__ out){
    int m = threadIdx.x;
    if (m >= 30) return;
    float v[3];
    #pragma unroll
    for (int c=0;c<3;c++){
        float acc = b[c];
        #pragma unroll
        for (int k=0;k<64;k++) acc = fmaf(g_c3[m*64+k], w[k*3+c], acc);
        v[c]=acc;
    }
    float mx = fmaxf(v[0], fmaxf(v[1],v[2]));
    float lse = mx + logf(expf(v[0]-mx)+expf(v[1]-mx)+expf(v[2]-mx));
    #pragma unroll
    for (int c=0;c<3;c++) out[m*3+c] = v[c]-lse;
}

extern "C" void kernel_launch(void* const* d_in, const int* in_sizes, int n_in,
                              void* d_out, int out_size){
    const float* x      = (const float*)d_in[0];
    const float* c1w    = (const float*)d_in[1];
    const float* c1b    = (const float*)d_in[2];
    const float* bn1g   = (const float*)d_in[3];
    const float* bn1b   = (const float*)d_in[4];
    const float* c2w    = (const float*)d_in[5];
    const float* c2b    = (const float*)d_in[6];
    const float* bn2g   = (const float*)d_in[7];
    const float* bn2b   = (const float*)d_in[8];
    const float* c3w    = (const float*)d_in[9];
    const float* c3b    = (const float*)d_in[10];
    const float* bn3g   = (const float*)d_in[11];
    const float* bn3b   = (const float*)d_in[12];
    const float* few    = (const float*)d_in[13];
    const float* feb    = (const float*)d_in[14];
    const float* s1w    = (const float*)d_in[15];
    const float* s1b    = (const float*)d_in[16];
    const float* s2w    = (const float*)d_in[17];
    const float* s2b    = (const float*)d_in[18];
    const float* s3w    = (const float*)d_in[19];
    const float* s3b    = (const float*)d_in[20];
    const float* s4w    = (const float*)d_in[21];
    const float* s4b    = (const float*)d_in[22];
    const float* clw1   = (const float*)d_in[23];
    const float* clb1   = (const float*)d_in[24];
    const float* clw2   = (const float*)d_in[25];
    const float* clb2   = (const float*)d_in[26];
    const float* clw3   = (const float*)d_in[27];
    const float* clb3   = (const float*)d_in[28];
    const float* clw4   = (const float*)d_in[29];
    const float* clb4   = (const float*)d_in[30];
    float* out = (float*)d_out;

    static int smem_set = 0;
    if (!smem_set){
        cudaFuncSetAttribute(kconv, cudaFuncAttributeMaxDynamicSharedMemorySize, 49024);
        smem_set = 1;
    }

    kconv<<<NROWS, 384, 49024>>>(x, c1w, c1b, bn1g, bn1b,
                                 c2w, c2b, bn2g, bn2b,
                                 c3w, c3b, bn3g, bn3b);
    k4a<<<dim3(64, K4_SPLIT), 256>>>(few);
    k4b<<<(NROWS*32 + 255)/256, 256>>>(feb);
    k5<<<((TOTPAIR/2) + 255)/256, 256>>>(s1w,s1b,s2w,s2b,s3w,s3b,s4w,s4b);
    k6a<<<dim3(32, K6_SPLIT), 256>>>(clw1);
    k6b<<<(30*1024 + 255)/256, 256>>>(clb1);
    k6c<<<dim3(30, 8), 256>>>(clw2, clb2);
    k6d<<<30, 256>>>(clw3, clb3);
    k6e<<<1, 32>>>(clw4, clb4, out);
}

// round 17
// speedup vs baseline: 1.0349x; 1.0349x over previous
#include <cuda_runtime.h>
#include <math.h>

#define NB 30
#define NODES 135
#define NROWS (NB*NODES)     // 4050
#define NPAIRS 9045
#define TOTPAIR (NB*NPAIRS)  // 271350

#define BN_S 0.9999950001f   // 1/sqrt(1+1e-5)
#define RRELU_S 0.2291666667f

#define K4_SPLIT 9
#define K6_SPLIT 16

typedef unsigned long long u64;

// ---- packed fp32x2 helpers (Blackwell FFMA2 path) ----
__device__ __forceinline__ u64 pk(float lo, float hi){
    u64 r; asm("mov.b64 %0, {%1,%2};" : "=l"(r) : "f"(lo), "f"(hi)); return r;
}
__device__ __forceinline__ void upk(u64 v, float& lo, float& hi){
    asm("mov.b64 {%0,%1}, %2;" : "=f"(lo), "=f"(hi) : "l"(v));
}
__device__ __forceinline__ u64 fma2(u64 a, u64 b, u64 c){
    u64 d; asm("fma.rn.f32x2 %0, %1, %2, %3;" : "=l"(d) : "l"(a), "l"(b), "l"(c)); return d;
}
__device__ __forceinline__ u64 add2(u64 a, u64 b){
    u64 d; asm("add.rn.f32x2 %0, %1, %2;" : "=l"(d) : "l"(a), "l"(b)); return d;
}

// ---- scratch ----
__device__ float g_s3[NROWS*48*45];          // [n][c*45+l]
__device__ float g_feats[NROWS*32];
__device__ float g_subj[NB*NPAIRS];
__device__ float g_p4[K4_SPLIT*NROWS*32];
__device__ float g_part[K6_SPLIT*NB*1024];
__device__ float g_c1[NB*1024];
__device__ float g_c2[NB*256];
__device__ float g_c3[NB*64];

__device__ __forceinline__ float leaky(float v){ return v > 0.f ? v : 0.01f*v; }

// ============================================================
// KCONV: fused conv1+conv2+conv3 per row. 384 threads (R15 winner). FROZEN.
// ============================================================
__global__ void kconv(const float* __restrict__ x,
      const float* __restrict__ w1, const float* __restrict__ cb1,
      const float* __restrict__ g1, const float* __restrict__ bb1,
      const float* __restrict__ w2, const float* __restrict__ cb2,
      const float* __restrict__ g2, const float* __restrict__ bb2,
      const float* __restrict__ w3, const float* __restrict__ cb3,
      const float* __restrict__ g3, const float* __restrict__ bb3){
    extern __shared__ float dsm[];
    float* s2s = dsm;                           // [0, 2944)
    float* s1s = dsm + 2944;                    // [2944, 5920) (phase A)
    u64*   wp2 = (u64*)(dsm + 2944 + 2976);     // 1568 u64 (phase A)
    u64*   wp3 = (u64*)(dsm + 2944);            // 4656 u64 (phase B)

    __shared__ float xr[376];
    __shared__ float ws1[96], A1[32], B1[32], A2[64], B2[64];

    int n = blockIdx.x, tid = threadIdx.x;
    const int NT = 384;

    for (int i=tid;i<375;i+=NT) xr[i] = x[n*375+i];
    if (tid < 96) ws1[tid] = w1[tid];
    if (tid < 32){ float a = g1[tid]*BN_S; A1[tid]=a; B1[tid]=fmaf(cb1[tid],a,bb1[tid]); }
    if (tid < 64){ float a = g2[tid]*BN_S; A2[tid]=a; B2[tid]=fmaf(cb2[tid],a,bb2[tid]); }
    for (int i=tid;i<1536;i+=NT){
        int c = i/48, r = i%48;
        wp2[c*49+r] = pk(w2[(2*c)*48 + r], w2[(2*c+1)*48 + r]);
    }
    __syncthreads();

    // ---- stage 1: x(375) -> s1s(16,186) ----
    for (int t=tid;t<2976;t+=NT){
        int c = t/186, l = t%186;
        float x0=xr[2*l], x1=xr[2*l+1], x2=xr[2*l+2], x3=xr[2*l+3];
        int c0=2*c, c1=2*c+1;
        float wa0=ws1[c0*3],wa1=ws1[c0*3+1],wa2=ws1[c0*3+2];
        float wb0=ws1[c1*3],wb1=ws1[c1*3+1],wb2=ws1[c1*3+2];
        float p00 = x0*wa0 + x1*wa1 + x2*wa2;
        float p01 = x1*wa0 + x2*wa1 + x3*wa2;
        float p10 = x0*wb0 + x1*wb1 + x2*wb2;
        float p11 = x1*wb0 + x2*wb1 + x3*wb2;
        float a0=A1[c0],b0=B1[c0],a1=A1[c1],b1=B1[c1];
        float v = fmaxf(fmaxf(leaky(fmaf(p00,a0,b0)), leaky(fmaf(p01,a0,b0))),
                        fmaxf(leaky(fmaf(p10,a1,b1)), leaky(fmaf(p11,a1,b1))));
        s1s[c*186+l] = v;
    }
    __syncthreads();

    // ---- stage 2: s1s(16,186) -> s2s(32,92). 368 tasks, 1 pass ----
    if (tid < 368){
        int c2 = tid & 15, lt = tid >> 4;
        int l0 = lt*4, px = 2*l0;
        u64 acA[8], acB[8];
        #pragma unroll
        for (int p=0;p<8;p++){ acA[p]=0ULL; acB[p]=0ULL; }
        const u64* wA = wp2 + c2*49;
        const u64* wB = wp2 + (c2+16)*49;
        for (int ci=0; ci<16; ci++){
            const float2* xp = (const float2*)(s1s + ci*186 + px);
            float xv[10];
            #pragma unroll
            for (int q=0;q<5;q++){ float2 v2 = xp[q]; xv[2*q]=v2.x; xv[2*q+1]=v2.y; }
            u64 xd[10];
            #pragma unroll
            for (int q=0;q<10;q++) xd[q] = pk(xv[q],xv[q]);
            u64 a0 = wA[ci*3], a1 = wA[ci*3+1], a2 = wA[ci*3+2];
            u64 b0 = wB[ci*3], b1 = wB[ci*3+1], b2 = wB[ci*3+2];
            #pragma unroll
            for (int p=0;p<8;p++){
                acA[p] = fma2(xd[p],a0, fma2(xd[p+1],a1, fma2(xd[p+2],a2, acA[p])));
                acB[p] = fma2(xd[p],b0, fma2(xd[p+1],b1, fma2(xd[p+2],b2, acB[p])));
            }
        }
        #pragma unroll
        for (int h=0;h<2;h++){
            int cp = c2 + 16*h;
            u64* ac = h ? acB : acA;
            float a0=A2[2*cp],b0=B2[2*cp],a1=A2[2*cp+1],b1=B2[2*cp+1];
            #pragma unroll
            for (int q=0;q<4;q++){
                float e0,o0,e1,o1;
                upk(ac[2*q], e0, o0);
                upk(ac[2*q+1], e1, o1);
                float v = fmaxf(fmaxf(leaky(fmaf(e0,a0,b0)), leaky(fmaf(e1,a0,b0))),
                                fmaxf(leaky(fmaf(o0,a1,b1)), leaky(fmaf(o1,a1,b1))));
                s2s[cp*92 + l0+q] = v;
            }
        }
    }
    __syncthreads();

    // ---- phase B weights ----
    for (int i=tid;i<4608;i+=NT){
        int c = i/96, r = i%96;
        wp3[c*97+r] = pk(w3[(2*c)*96 + r], w3[(2*c+1)*96 + r]);
    }
    __syncthreads();

    // ---- stage 3: s2s(32,92) -> g_s3. 24 grp(2 pairs) x 15 lt = 360 ----
    if (tid < 360){
        int g = tid % 24, lt = tid / 24;
        int l0 = lt*3, px = 2*l0;
        u64 ac[2][6];
        #pragma unroll
        for (int h=0;h<2;h++)
            #pragma unroll
            for (int p=0;p<6;p++) ac[h][p]=0ULL;
        const u64* wA = wp3 + (2*g)*97;
        const u64* wB = wp3 + (2*g+1)*97;
        for (int ci=0; ci<32; ci++){
            const float2* xp = (const float2*)(s2s + ci*92 + px);
            float xv[8];
            #pragma unroll
            for (int q=0;q<4;q++){ float2 v2 = xp[q]; xv[2*q]=v2.x; xv[2*q+1]=v2.y; }
            u64 xd[8];
            #pragma unroll
            for (int q=0;q<8;q++) xd[q] = pk(xv[q],xv[q]);
            u64 a0 = wA[ci*3], a1 = wA[ci*3+1], a2 = wA[ci*3+2];
            u64 b0 = wB[ci*3], b1 = wB[ci*3+1], b2 = wB[ci*3+2];
            #pragma unroll
            for (int p=0;p<6;p++){
                ac[0][p] = fma2(xd[p],a0, fma2(xd[p+1],a1, fma2(xd[p+2],a2, ac[0][p])));
                ac[1][p] = fma2(xd[p],b0, fma2(xd[p+1],b1, fma2(xd[p+2],b2, ac[1][p])));
            }
        }
        #pragma unroll
        for (int h=0;h<2;h++){
            int cp = 2*g + h;
            int c0=2*cp, c1=2*cp+1;
            float a0=__ldg(g3+c0)*BN_S, a1=__ldg(g3+c1)*BN_S;
            float b0=fmaf(__ldg(cb3+c0),a0,__ldg(bb3+c0));
            float b1=fmaf(__ldg(cb3+c1),a1,__ldg(bb3+c1));
            #pragma unroll
            for (int q=0;q<3;q++){
                float e0,o0,e1,o1;
                upk(ac[h][2*q], e0, o0);
                upk(ac[h][2*q+1], e1, o1);
                float v = fmaxf(fmaxf(leaky(fmaf(e0,a0,b0)), leaky(fmaf(e1,a0,b0))),
                                fmaxf(leaky(fmaf(o0,a1,b1)), leaky(fmaf(o1,a1,b1))));
                g_s3[(n*48+cp)*45 + l0+q] = v;
            }
        }
    }
}

// ============================================================
// K4a: split-K GEMM: s3(4050,2160) @ W(2160,32), smem h-tile (R15, no prefetch).
// ============================================================
__global__ void k4a(const float* __restrict__ w){
    __shared__ float h_s[64*52];        // 13312 B
    __shared__ u64   ws2[48*16];        // 6144 B
    int tid = threadIdx.x;
    int o4 = tid & 7, rg = tid >> 3;
    int n0 = blockIdx.x * 64;
    int r0 = 2*rg, r1 = 2*rg+1;
    int ks = blockIdx.y * 240;
    u64 a00=0ULL, a01=0ULL, a10=0ULL, a11=0ULL;
    for (int c0 = 0; c0 < 240; c0 += 48){
        __syncthreads();
        for (int i = tid; i < 384; i += 256){
            int kk = i >> 3, j = i & 7;
            float4 f = ((const float4*)(w + (ks + c0 + kk)*32))[j];
            ws2[kk*16 + 2*j]   = pk(f.x, f.y);
            ws2[kk*16 + 2*j+1] = pk(f.z, f.w);
        }
        for (int i = tid; i < 768; i += 256){
            int row = i / 12, k4i = i % 12;
            int nn = n0 + row; if (nn >= NROWS) nn = NROWS-1;
            float4 v = *(const float4*)(g_s3 + (size_t)nn*2160 + ks + c0 + 4*k4i);
            *(float4*)(h_s + row*52 + 4*k4i) = v;
        }
        __syncthreads();
        #pragma unroll
        for (int kk = 0; kk < 48; kk++){
            ulonglong2 wv = *(const ulonglong2*)&ws2[kk*16 + 2*o4];
            float ha = h_s[r0*52 + kk];
            float hb = h_s[r1*52 + kk];
            u64 had = pk(ha, ha), hbd = pk(hb, hb);
            a00 = fma2(had, wv.x, a00);
            a01 = fma2(had, wv.y, a01);
            a10 = fma2(hbd, wv.x, a10);
            a11 = fma2(hbd, wv.y, a11);
        }
    }
    float e0,o0,e1,o1;
    int n = n0 + r0;
    if (n < NROWS){
        upk(a00, e0, o0); upk(a01, e1, o1);
        *(float4*)(g_p4 + ((size_t)blockIdx.y*NROWS + n)*32 + 4*o4) = make_float4(e0,o0,e1,o1);
    }
    n = n0 + r1;
    if (n < NROWS){
        upk(a10, e0, o0); upk(a11, e1, o1);
        *(float4*)(g_p4 + ((size_t)blockIdx.y*NROWS + n)*32 + 4*o4) = make_float4(e0,o0,e1,o1);
    }
}

__global__ void k4b(const float* __restrict__ b){
    int idx = blockIdx.x*blockDim.x + threadIdx.x;
    if (idx >= NROWS*32) return;
    int o = idx & 31;
    float s = b[o];
    #pragma unroll
    for (int q=0;q<K4_SPLIT;q++) s += g_p4[(size_t)q*NROWS*32 + idx];
    g_feats[idx] = s;
}

// ============================================================
// K5: sim MLP, 2 pairs per thread, per-batch feats staged in smem
// (row stride 36 -> spread banks). Grid (18 pair-tiles, 30 batches).
// ============================================================
__device__ __forceinline__ void decode_pair_b(int p, int& i, int& j){
    int ii = (int)((269.0f - sqrtf(72361.0f - 8.0f*(float)p)) * 0.5f);
    if (ii < 0) ii = 0; if (ii > 133) ii = 133;
    while (ii > 0   && (ii*(269-ii))/2 > p) ii--;
    while (ii < 133 && ((ii+1)*(268-ii))/2 <= p) ii++;
    i = ii;
    j = ii + 1 + (p - (ii*(269-ii))/2);
}

__global__ void k5(const float* __restrict__ w1, const float* __restrict__ b1,
                   const float* __restrict__ w2, const float* __restrict__ b2,
                   const float* __restrict__ w3, const float* __restrict__ b3,
                   const float* __restrict__ w4, const float* __restrict__ b4){
    __shared__ float fs[135*36];        // 19440 B, stride 36
    __shared__ u64 w1u[1024], w2u[256], w3u[64];
    __shared__ float w4s[8], b1s[32], b2s[16], b3s[8];
    __shared__ float b4s;
    int tid = threadIdx.x;
    int b = blockIdx.y;
    // stage this batch's features: 135 nodes x 8 float4
    for (int i=tid;i<1080;i+=256){
        int node = i >> 3, q = i & 7;
        float4 v = ((const float4*)(g_feats + (b*135+node)*32))[q];
        *(float4*)(fs + node*36 + 4*q) = v;
    }
    for (int i=tid;i<1024;i+=256){ float2 v = *(const float2*)(w1+2*i); w1u[i]=pk(v.x,v.y); }
    if (tid<256){ float2 v = *(const float2*)(w2+2*tid); w2u[tid]=pk(v.x,v.y); }
    if (tid<64) { float2 v = *(const float2*)(w3+2*tid); w3u[tid]=pk(v.x,v.y); }
    if (tid<32)  b1s[tid]=b1[tid];
    if (tid<16)  b2s[tid]=b2[tid];
    if (tid<8)   { w4s[tid]=w4[tid]; b3s[tid]=b3[tid]; }
    if (tid==0)  b4s=b4[0];
    __syncthreads();
    int p0 = blockIdx.x*512 + tid*2;
    if (p0 >= NPAIRS) return;
    int p1 = p0 + 1;
    bool has1 = p1 < NPAIRS;
    int pb1 = has1 ? p1 : p0;
    int i0,j0,i1,j1;
    decode_pair_b(p0, i0, j0);
    decode_pair_b(pb1, i1, j1);
    const float4* fi0 = (const float4*)(fs + i0*36);
    const float4* fj0 = (const float4*)(fs + j0*36);
    const float4* fi1 = (const float4*)(fs + i1*36);
    const float4* fj1 = (const float4*)(fs + j1*36);

    u64 A0[16], A1[16];
    #pragma unroll
    for (int o=0;o<16;o++){ u64 bb = pk(b1s[2*o], b1s[2*o+1]); A0[o]=bb; A1[o]=bb; }
    #pragma unroll
    for (int q=0;q<8;q++){
        float4 f0 = fi0[q], f1 = fi1[q];
        float fv0[4] = {f0.x,f0.y,f0.z,f0.w};
        float fv1[4] = {f1.x,f1.y,f1.z,f1.w};
        #pragma unroll
        for (int s=0;s<4;s++){
            u64 v0 = pk(fv0[s], fv0[s]);
            u64 v1 = pk(fv1[s], fv1[s]);
            int t = 4*q+s;
            #pragma unroll
            for (int o=0;o<16;o++){
                u64 ww = w1u[t*16+o];
                A0[o] = fma2(v0, ww, A0[o]);
                A1[o] = fma2(v1, ww, A1[o]);
            }
        }
    }
    #pragma unroll
    for (int q=0;q<8;q++){
        float4 f0 = fj0[q], f1 = fj1[q];
        float fv0[4] = {f0.x,f0.y,f0.z,f0.w};
        float fv1[4] = {f1.x,f1.y,f1.z,f1.w};
        #pragma unroll
        for (int s=0;s<4;s++){
            u64 v0 = pk(fv0[s], fv0[s]);
            u64 v1 = pk(fv1[s], fv1[s]);
            int t = 32 + 4*q+s;
            #pragma unroll
            for (int o=0;o<16;o++){
                u64 ww = w1u[t*16+o];
                A0[o] = fma2(v0, ww, A0[o]);
                A1[o] = fma2(v1, ww, A1[o]);
            }
        }
    }
    float h10[32], h11[32];
    #pragma unroll
    for (int o=0;o<16;o++){
        float e,od;
        upk(A0[o],e,od); h10[2*o]=fmaxf(e,0.f); h10[2*o+1]=fmaxf(od,0.f);
        upk(A1[o],e,od); h11[2*o]=fmaxf(e,0.f); h11[2*o+1]=fmaxf(od,0.f);
    }
    u64 B0[8], B1[8];
    #pragma unroll
    for (int o=0;o<8;o++){ u64 bb = pk(b2s[2*o], b2s[2*o+1]); B0[o]=bb; B1[o]=bb; }
    #pragma unroll
    for (int t=0;t<32;t++){
        u64 v0 = pk(h10[t], h10[t]);
        u64 v1 = pk(h11[t], h11[t]);
        #pragma unroll
        for (int o=0;o<8;o++){
            u64 ww = w2u[t*8+o];
            B0[o] = fma2(v0, ww, B0[o]);
            B1[o] = fma2(v1, ww, B1[o]);
        }
    }
    float h20[16], h21[16];
    #pragma unroll
    for (int o=0;o<8;o++){
        float e,od;
        upk(B0[o],e,od); h20[2*o]=fmaxf(e,0.f); h20[2*o+1]=fmaxf(od,0.f);
        upk(B1[o],e,od); h21[2*o]=fmaxf(e,0.f); h21[2*o+1]=fmaxf(od,0.f);
    }
    u64 C0[4], C1[4];
    #pragma unroll
    for (int o=0;o<4;o++){ u64 bb = pk(b3s[2*o], b3s[2*o+1]); C0[o]=bb; C1[o]=bb; }
    #pragma unroll
    for (int t=0;t<16;t++){
        u64 v0 = pk(h20[t], h20[t]);
        u64 v1 = pk(h21[t], h21[t]);
        #pragma unroll
        for (int o=0;o<4;o++){
            u64 ww = w3u[t*4+o];
            C0[o] = fma2(v0, ww, C0[o]);
            C1[o] = fma2(v1, ww, C1[o]);
        }
    }
    float o40 = b4s, o41 = b4s;
    #pragma unroll
    for (int o=0;o<4;o++){
        float e,od;
        upk(C0[o],e,od);
        o40 = fmaf(fmaxf(e,0.f),  w4s[2*o],   o40);
        o40 = fmaf(fmaxf(od,0.f), w4s[2*o+1], o40);
        upk(C1[o],e,od);
        o41 = fmaf(fmaxf(e,0.f),  w4s[2*o],   o41);
        o41 = fmaf(fmaxf(od,0.f), w4s[2*o+1], o41);
    }
    g_subj[b*NPAIRS + p0] = tanhf(o40);
    if (has1) g_subj[b*NPAIRS + p1] = tanhf(o41);
}

// ============================================================
// K6a: split-K GEMM partials: (30,9045)@(9045,1024). (R15, no prefetch)
// ============================================================
__global__ void k6a(const float* __restrict__ w){
    __shared__ __align__(16) char sbuf[33792];
    u64*   ssub2 = (u64*)sbuf;                 // 128*17 u64 = 17408 B
    float* wt    = (float*)(sbuf + 17408);     // 128*32 f   = 16384 B
    u64*   red   = (u64*)sbuf;                 // 256*15 u64 = 30720 B (post-loop)
    int tid = threadIdx.x;
    int lane = tid & 31, kg = tid >> 5;
    int nb = blockIdx.x*32;
    int kstart = blockIdx.y*566;
    int kend = min(9045, kstart+566);
    u64 accp[15];
    #pragma unroll
    for (int m=0;m<15;m++) accp[m]=0ULL;
    for (int k0=kstart;k0<kend;k0+=128){
        int clen = min(128, kend-k0);
        __syncthreads();
        for (int i=tid;i<15*128;i+=256){
            int m = i>>7, kk = i&127;
            float v0=0.f, v1=0.f;
            if (kk<clen){
                v0 = g_subj[(2*m)*9045 + k0+kk];
                v1 = g_subj[(2*m+1)*9045 + k0+kk];
            }
            ssub2[kk*17+m] = pk(v0,v1);
        }
        for (int i=tid;i<1024;i+=256){
            int kk = i>>3, j = i&7;
            float4 f = make_float4(0.f,0.f,0.f,0.f);
            if (kk < clen)
                f = ((const float4*)(w + (size_t)(k0+kk)*1024 + nb))[j];
            ((float4*)(wt + kk*32))[j] = f;
        }
        __syncthreads();
        for (int kk=kg; kk<clen; kk+=8){
            float wv = wt[kk*32 + lane];
            u64 wv2 = pk(wv,wv);
            #pragma unroll
            for (int m=0;m<15;m++) accp[m] = fma2(ssub2[kk*17+m], wv2, accp[m]);
        }
    }
    __syncthreads();
    #pragma unroll
    for (int m=0;m<15;m++) red[tid*15+m] = accp[m];
    __syncthreads();
    for (int it=tid; it<32*15; it+=256){
        int l2 = it/15, mp = it%15;
        u64 s = red[l2*15+mp];
        #pragma unroll
        for (int q=1;q<8;q++) s = add2(s, red[(q*32+l2)*15+mp]);
        float e,o; upk(s,e,o);
        g_part[((size_t)blockIdx.y*30+2*mp)*1024   + nb + l2] = e;
        g_part[((size_t)blockIdx.y*30+2*mp+1)*1024 + nb + l2] = o;
    }
}

__global__ void k6b(const float* __restrict__ b){
    int idx = blockIdx.x*blockDim.x+threadIdx.x;
    if (idx >= 30*1024) return;
    int m = idx>>10, o = idx&1023;
    float s = b[o];
    #pragma unroll
    for (int q=0;q<K6_SPLIT;q++) s += g_part[((size_t)q*30+m)*1024+o];
    g_c1[idx] = (s >= 0.f) ? s : RRELU_S*s;
}

__global__ void k6c(const float* __restrict__ w, const float* __restrict__ b){
    __shared__ float red[256];
    int m = blockIdx.x, og = blockIdx.y;
    int tid = threadIdx.x;
    int ol = tid & 31, kg = tid >> 5;
    int o = og*32 + ol;
    const float* c1 = g_c1 + m*1024;
    float acc = 0.f;
    #pragma unroll 8
    for (int k = kg; k < 1024; k += 8)
        acc = fmaf(c1[k], w[k*256 + o], acc);
    red[tid] = acc;
    __syncthreads();
    if (tid < 32){
        float s = b[og*32 + tid];
        #pragma unroll
        for (int q=0;q<8;q++) s += red[q*32 + tid];
        g_c2[m*256 + og*32 + tid] = fmaxf(s, 0.f);
    }
}

__global__ void k6d(const float* __restrict__ w, const float* __restrict__ b){
    __shared__ float red[256];
    int m = blockIdx.x;
    int tid = threadIdx.x;
    int o = tid & 63, kg = tid >> 6;
    const float* c2 = g_c2 + m*256;
    float acc = 0.f;
    #pragma unroll 8
    for (int k = kg; k < 256; k += 4)
        acc = fmaf(c2[k], w[k*64 + o], acc);
    red[tid] = acc;
    __syncthreads();
    if (tid < 64){
        float s = b[tid] + red[tid] + red[64+tid] + red[128+tid] + red[192+tid];
        g_c3[m*64 + tid] = fmaxf(s, 0.f);
    }
}

__global__ void k6e(const float* __restrict__ w, const float* __restrict__ b,
                    float* __restrict__ out){
    int m = threadIdx.x;
    if (m >= 30) return;
    float v[3];
    #pragma unroll
    for (int c=0;c<3;c++){
        float acc = b[c];
        #pragma unroll
        for (int k=0;k<64;k++) acc = fmaf(g_c3[m*64+k], w[k*3+c], acc);
        v[c]=acc;
    }
    float mx = fmaxf(v[0], fmaxf(v[1],v[2]));
    float lse = mx + logf(expf(v[0]-mx)+expf(v[1]-mx)+expf(v[2]-mx));
    #pragma unroll
    for (int c=0;c<3;c++) out[m*3+c] = v[c]-lse;
}

extern "C" void kernel_launch(void* const* d_in, const int* in_sizes, int n_in,
                              void* d_out, int out_size){
    const float* x      = (const float*)d_in[0];
    const float* c1w    = (const float*)d_in[1];
    const float* c1b    = (const float*)d_in[2];
    const float* bn1g   = (const float*)d_in[3];
    const float* bn1b   = (const float*)d_in[4];
    const float* c2w    = (const float*)d_in[5];
    const float* c2b    = (const float*)d_in[6];
    const float* bn2g   = (const float*)d_in[7];
    const float* bn2b   = (const float*)d_in[8];
    const float* c3w    = (const float*)d_in[9];
    const float* c3b    = (const float*)d_in[10];
    const float* bn3g   = (const float*)d_in[11];
    const float* bn3b   = (const float*)d_in[12];
    const float* few    = (const float*)d_in[13];
    const float* feb    = (const float*)d_in[14];
    const float* s1w    = (const float*)d_in[15];
    const float* s1b    = (const float*)d_in[16];
    const float* s2w    = (const float*)d_in[17];
    const float* s2b    = (const float*)d_in[18];
    const float* s3w    = (const float*)d_in[19];
    const float* s3b    = (const float*)d_in[20];
    const float* s4w    = (const float*)d_in[21];
    const float* s4b    = (const float*)d_in[22];
    const float* clw1   = (const float*)d_in[23];
    const float* clb1   = (const float*)d_in[24];
    const float* clw2   = (const float*)d_in[25];
    const float* clb2   = (const float*)d_in[26];
    const float* clw3   = (const float*)d_in[27];
    const float* clb3   = (const float*)d_in[28];
    const float* clw4   = (const float*)d_in[29];
    const float* clb4   = (const float*)d_in[30];
    float* out = (float*)d_out;

    static int smem_set = 0;
    if (!smem_set){
        cudaFuncSetAttribute(kconv, cudaFuncAttributeMaxDynamicSharedMemorySize, 49024);
        smem_set = 1;
    }

    kconv<<<NROWS, 384, 49024>>>(x, c1w, c1b, bn1g, bn1b,
                                 c2w, c2b, bn2g, bn2b,
                                 c3w, c3b, bn3g, bn3b);
    k4a<<<dim3(64, K4_SPLIT), 256>>>(few);
    k4b<<<(NROWS*32 + 255)/256, 256>>>(feb);
    k5<<<dim3(18, NB), 256>>>(s1w,s1b,s2w,s2b,s3w,s3b,s4w,s4b);
    k6a<<<dim3(32, K6_SPLIT), 256>>>(clw1);
    k6b<<<(30*1024 + 255)/256, 256>>>(clb1);
    k6c<<<dim3(30, 8), 256>>>(clw2, clb2);
    k6d<<<30, 256>>>(clw3, clb3);
    k6e<<<1, 32>>>(clw4, clb4, out);
}